// round 10
// baseline (speedup 1.0000x reference)
#include <cuda_runtime.h>
#include <cuda_fp16.h>
#include <cstdint>

#define NEG_BIG (-9000000000000000.0f)
#define LEAKY 0.2f

// ---- scratch (static device globals; no runtime allocation) ----
__device__ __half g_WhT [8ul * 256 * 2048];    // [b][n][i] half (B operand / AV)
__device__ __half g_P   [8ul * 2048 * 2048];   // normalized attention, half
__device__ __half g_hh  [8ul * 2048 * 256];    // h hi half
__device__ __half g_hl  [8ul * 2048 * 256];    // h lo half
__device__ __half g_wh2 [256 * 256];           // W hi half
__device__ __half g_wl  [256 * 256];           // W lo half
__device__ float  g_s1  [8 * 2048];
__device__ float  g_s2  [8 * 2048];
__device__ float  g_wa1 [256];
__device__ float  g_wa2 [256];

__device__ __forceinline__ unsigned sptr(const void* p) {
    return (unsigned)__cvta_generic_to_shared(p);
}
#define CP_ASYNC16(dst, src) \
    asm volatile("cp.async.cg.shared.global [%0], [%1], 16;" :: "r"(dst), "l"(src))
#define CP_COMMIT() asm volatile("cp.async.commit_group;")
#define CP_WAIT0()  asm volatile("cp.async.wait_group 0;")
#define CP_WAIT1()  asm volatile("cp.async.wait_group 1;")
#define CP_WAIT2()  asm volatile("cp.async.wait_group 2;")

__device__ __forceinline__ void ldsm_x4(uint32_t& r0, uint32_t& r1,
                                        uint32_t& r2, uint32_t& r3,
                                        uint32_t addr) {
    asm volatile("ldmatrix.sync.aligned.m8n8.x4.shared.b16 {%0,%1,%2,%3}, [%4];"
                 : "=r"(r0), "=r"(r1), "=r"(r2), "=r"(r3) : "r"(addr));
}
__device__ __forceinline__ void mma_f16(float* d, const uint32_t* a, const uint32_t* b) {
    asm volatile(
        "mma.sync.aligned.m16n8k16.row.col.f32.f16.f16.f32 "
        "{%0,%1,%2,%3}, {%4,%5,%6,%7}, {%8,%9}, {%0,%1,%2,%3};"
        : "+f"(d[0]), "+f"(d[1]), "+f"(d[2]), "+f"(d[3])
        : "r"(a[0]), "r"(a[1]), "r"(a[2]), "r"(a[3]), "r"(b[0]), "r"(b[1]));
}

// hi/lo split of a float4 into two packed half4 (8B each)
__device__ __forceinline__ void split4(float4 v, uint2& hi, uint2& lo) {
    __half hx = __float2half_rn(v.x), hy = __float2half_rn(v.y);
    __half hz = __float2half_rn(v.z), hw = __float2half_rn(v.w);
    __half lx = __float2half_rn(v.x - __half2float(hx));
    __half ly = __float2half_rn(v.y - __half2float(hy));
    __half lz = __float2half_rn(v.z - __half2float(hz));
    __half lw = __float2half_rn(v.w - __half2float(hw));
    __half2 h01 = __halves2half2(hx, hy), h23 = __halves2half2(hz, hw);
    __half2 l01 = __halves2half2(lx, ly), l23 = __halves2half2(lz, lw);
    hi = make_uint2(*(uint32_t*)&h01, *(uint32_t*)&h23);
    lo = make_uint2(*(uint32_t*)&l01, *(uint32_t*)&l23);
}

// ============================================================
// Kernel 0a/0b: hi/lo split of h and W
// ============================================================
__global__ void k_split(const float* __restrict__ h) {
    size_t i4 = (size_t)blockIdx.x * 256 + threadIdx.x;   // float4 index
    float4 v = *((const float4*)h + i4);
    uint2 hi, lo;
    split4(v, hi, lo);
    *((uint2*)g_hh + i4) = hi;
    *((uint2*)g_hl + i4) = lo;
}
__global__ void k_splitW(const float* __restrict__ W) {
    size_t i4 = (size_t)blockIdx.x * 256 + threadIdx.x;
    float4 v = *((const float4*)W + i4);
    uint2 hi, lo;
    split4(v, hi, lo);
    *((uint2*)g_wh2 + i4) = hi;
    *((uint2*)g_wl  + i4) = lo;
}

// ============================================================
// Kernel 0c: wa1 = W^T a1, wa2 = W^T a2   (single block)
// ============================================================
__global__ void k_wa(const float* __restrict__ W, const float* __restrict__ a) {
    int f = threadIdx.x;
    float v1 = 0.0f, v2 = 0.0f;
#pragma unroll 8
    for (int o = 0; o < 256; o++) {
        float w = W[o * 256 + f];
        v1 = fmaf(w, __ldg(a + o),       v1);
        v2 = fmaf(w, __ldg(a + 256 + o), v2);
    }
    g_wa1[f] = v1;
    g_wa2[f] = v2;
}

// ============================================================
// Kernel 1: s1[r] = h[r,:]·wa1 ; s2[r] = h[r,:]·wa2  (exact fp32)
// ============================================================
__global__ void k_s(const float* __restrict__ h) {
    int row  = blockIdx.x * 8 + (threadIdx.x >> 5);
    int lane = threadIdx.x & 31;
    const float* hr = h + (size_t)row * 256;

    float v1 = 0.0f, v2 = 0.0f;
#pragma unroll
    for (int k = lane; k < 256; k += 32) {
        float x = hr[k];
        v1 = fmaf(x, g_wa1[k], v1);
        v2 = fmaf(x, g_wa2[k], v2);
    }
#pragma unroll
    for (int off = 16; off; off >>= 1) {
        v1 += __shfl_down_sync(0xffffffffu, v1, off);
        v2 += __shfl_down_sync(0xffffffffu, v2, off);
    }
    if (lane == 0) { g_s1[row] = v1; g_s2[row] = v2; }
}

// ============================================================
// Kernel 2: WhT[b][n][i] = sum_f W[n][f] h[b][i][f]
//   fp16 mma on pre-split hi/lo (3 MMA passes: hh + hl + lh).
//   BM=128(n) x BN=64(i), BK=32, NSTAGE=3, 1 barrier/ktile.
// ============================================================
#define G_STRIDE 40
#define G_ABUF (128 * G_STRIDE)     // halves per A tile (hi or lo)
#define G_BBUF (64  * G_STRIDE)
#define G_NSTAGE 3

__global__ __launch_bounds__(256, 2) void k_gemm16() {
    extern __shared__ __half gsm[];
    __half* Ah = gsm;
    __half* Al = Ah + G_NSTAGE * G_ABUF;
    __half* Bh = Al + G_NSTAGE * G_ABUF;
    __half* Bl = Bh + G_NSTAGE * G_BBUF;

    int tid = threadIdx.x;
    int wid = tid >> 5, lane = tid & 31;
    int g = lane >> 2, tig = lane & 3;
    int warpM = wid & 3;            // 4 x 32 n-rows
    int warpN = wid >> 2;           // 2 x 32 i-cols

    int i0 = blockIdx.x * 64;
    int b  = blockIdx.y >> 1;
    int n0 = (blockIdx.y & 1) * 128;

    // cp.async: A 512 chunks (2/thread each hi/lo), B 256 (1/thread each)
    const __half* ah_src[2]; const __half* al_src[2];
    uint32_t ah_dst[2], al_dst[2];
#pragma unroll
    for (int p = 0; p < 2; p++) {
        int c = tid + p * 256;
        int row = c >> 2, q = c & 3;
        size_t go = (size_t)(n0 + row) * 256 + q * 8;
        ah_src[p] = g_wh2 + go;
        al_src[p] = g_wl  + go;
        ah_dst[p] = sptr(Ah + row * G_STRIDE + q * 8);
        al_dst[p] = sptr(Al + row * G_STRIDE + q * 8);
    }
    const __half* bh_src; const __half* bl_src;
    uint32_t bh_dst, bl_dst;
    {
        int row = tid >> 2, q = tid & 3;
        size_t go = ((size_t)(b * 2048 + i0 + row)) * 256 + q * 8;
        bh_src = g_hh + go;
        bl_src = g_hl + go;
        bh_dst = sptr(Bh + row * G_STRIDE + q * 8);
        bl_dst = sptr(Bl + row * G_STRIDE + q * 8);
    }

    // ldsm lane addressing
    uint32_t a_ld[2][2], b_ld[2];
    {
        int arow = lane & 15;
        int akh  = (lane >> 4) * 8;
        int brow = (lane & 7) + ((lane >> 4) & 1) * 8;
        int bkh  = ((lane >> 3) & 1) * 8;
#pragma unroll
        for (int kc = 0; kc < 2; kc++) {
#pragma unroll
            for (int mt = 0; mt < 2; mt++)
                a_ld[mt][kc] = (uint32_t)((warpM * 32 + mt * 16 + arow) * G_STRIDE
                                          + kc * 16 + akh) * 2;
            b_ld[kc] = (uint32_t)((warpN * 32 + brow) * G_STRIDE + kc * 16 + bkh) * 2;
        }
    }
    uint32_t AhB = sptr(Ah), AlB = sptr(Al), BhB = sptr(Bh), BlB = sptr(Bl);

    float acc[2][4][4];
#pragma unroll
    for (int mt = 0; mt < 2; mt++)
#pragma unroll
        for (int nt = 0; nt < 4; nt++)
#pragma unroll
            for (int c = 0; c < 4; c++) acc[mt][nt][c] = 0.0f;

    const uint32_t ASB = G_ABUF * 2;    // stage stride bytes
    const uint32_t BSB = G_BBUF * 2;

    auto issue_tile = [&](int k0, int st) {
#pragma unroll
        for (int p = 0; p < 2; p++) {
            CP_ASYNC16(ah_dst[p] + st * ASB, ah_src[p] + k0);
            CP_ASYNC16(al_dst[p] + st * ASB, al_src[p] + k0);
        }
        CP_ASYNC16(bh_dst + st * BSB, bh_src + k0);
        CP_ASYNC16(bl_dst + st * BSB, bl_src + k0);
        CP_COMMIT();
    };

    issue_tile(0, 0);
    issue_tile(32, 1);

#pragma unroll 1
    for (int t = 0; t < 8; t++) {
        int st = t % 3;
        if (t + 2 < 8) { CP_WAIT1(); } else { CP_WAIT0(); }
        __syncthreads();
        if (t + 2 < 8) issue_tile((t + 2) * 32, (t + 2) % 3);

        uint32_t as = st * ASB, bs = st * BSB;

#pragma unroll
        for (int kc = 0; kc < 2; kc++) {
            uint32_t afh[2][4], afl[2][4];
#pragma unroll
            for (int mt = 0; mt < 2; mt++) {
                ldsm_x4(afh[mt][0], afh[mt][1], afh[mt][2], afh[mt][3],
                        AhB + as + a_ld[mt][kc]);
                ldsm_x4(afl[mt][0], afl[mt][1], afl[mt][2], afl[mt][3],
                        AlB + as + a_ld[mt][kc]);
            }
            uint32_t bfh[4][2], bfl[4][2];
            {
                uint32_t r0, r1, r2, r3;
                ldsm_x4(r0, r1, r2, r3, BhB + bs + b_ld[kc]);
                bfh[0][0] = r0; bfh[0][1] = r1; bfh[1][0] = r2; bfh[1][1] = r3;
                ldsm_x4(r0, r1, r2, r3, BhB + bs + b_ld[kc] + 16 * G_STRIDE * 2);
                bfh[2][0] = r0; bfh[2][1] = r1; bfh[3][0] = r2; bfh[3][1] = r3;
                ldsm_x4(r0, r1, r2, r3, BlB + bs + b_ld[kc]);
                bfl[0][0] = r0; bfl[0][1] = r1; bfl[1][0] = r2; bfl[1][1] = r3;
                ldsm_x4(r0, r1, r2, r3, BlB + bs + b_ld[kc] + 16 * G_STRIDE * 2);
                bfl[2][0] = r0; bfl[2][1] = r1; bfl[3][0] = r2; bfl[3][1] = r3;
            }
#pragma unroll
            for (int mt = 0; mt < 2; mt++)
#pragma unroll
                for (int nt = 0; nt < 4; nt++) {
                    mma_f16(acc[mt][nt], afh[mt], bfh[nt]);
                    mma_f16(acc[mt][nt], afh[mt], bfl[nt]);
                    mma_f16(acc[mt][nt], afl[mt], bfh[nt]);
                }
        }
    }

    // epilogue: half store (n rows, i cols)
#pragma unroll
    for (int mt = 0; mt < 2; mt++) {
#pragma unroll
        for (int nt = 0; nt < 4; nt++) {
            int n = n0 + warpM * 32 + mt * 16 + g;
            int i = i0 + warpN * 32 + nt * 8 + 2 * tig;
            __half2 v0 = __floats2half2_rn(acc[mt][nt][0], acc[mt][nt][1]);
            __half2 v1 = __floats2half2_rn(acc[mt][nt][2], acc[mt][nt][3]);
            *(__half2*)(g_WhT + ((size_t)(b * 256 + n))     * 2048 + i) = v0;
            *(__half2*)(g_WhT + ((size_t)(b * 256 + n + 8)) * 2048 + i) = v1;
        }
    }
}

// ============================================================
// Kernel 3: masked-leaky softmax, register-resident
// ============================================================
__global__ __launch_bounds__(256) void k_softmax(const int* __restrict__ adj) {
    __shared__ float redm[8];
    __shared__ float redsum[8];

    int i = blockIdx.x;
    int b = blockIdx.y;
    int tid  = threadIdx.x;
    int wid  = tid >> 5;
    int lane = tid & 31;

    const int4*  arow4 = (const int4*)(adj + ((size_t)b * 2048 + i) * 2048);
    const float* s2    = g_s2 + (size_t)b * 2048;
    float s1i = g_s1[(size_t)b * 2048 + i];

    float e[8];
    float lm = -INFINITY;
#pragma unroll
    for (int c = 0; c < 2; c++) {
        int jv = tid + c * 256;
        int4   av  = arow4[jv];
        float4 s2v = *(const float4*)(s2 + jv * 4);
        float e0 = s1i + s2v.x, e1 = s1i + s2v.y;
        float e2 = s1i + s2v.z, e3 = s1i + s2v.w;
        e0 = (e0 > 0.0f) ? e0 : LEAKY * e0;
        e1 = (e1 > 0.0f) ? e1 : LEAKY * e1;
        e2 = (e2 > 0.0f) ? e2 : LEAKY * e2;
        e3 = (e3 > 0.0f) ? e3 : LEAKY * e3;
        e0 = av.x ? e0 : NEG_BIG;
        e1 = av.y ? e1 : NEG_BIG;
        e2 = av.z ? e2 : NEG_BIG;
        e3 = av.w ? e3 : NEG_BIG;
        e[c * 4 + 0] = e0; e[c * 4 + 1] = e1;
        e[c * 4 + 2] = e2; e[c * 4 + 3] = e3;
        lm = fmaxf(lm, fmaxf(fmaxf(e0, e1), fmaxf(e2, e3)));
    }
#pragma unroll
    for (int off = 16; off; off >>= 1)
        lm = fmaxf(lm, __shfl_xor_sync(0xffffffffu, lm, off));
    if (lane == 0) redm[wid] = lm;
    __syncthreads();

    float m = redm[0];
#pragma unroll
    for (int w = 1; w < 8; w++) m = fmaxf(m, redm[w]);

    float ls = 0.0f;
#pragma unroll
    for (int t = 0; t < 8; t++) {
        float p = __expf(e[t] - m);
        e[t] = p;
        ls += p;
    }
#pragma unroll
    for (int off = 16; off; off >>= 1)
        ls += __shfl_xor_sync(0xffffffffu, ls, off);
    if (lane == 0) redsum[wid] = ls;
    __syncthreads();

    float sum = 0.0f;
#pragma unroll
    for (int w = 0; w < 8; w++) sum += redsum[w];
    float rinv = 1.0f / sum;

    __half* prow = g_P + ((size_t)b * 2048 + i) * 2048;
#pragma unroll
    for (int c = 0; c < 2; c++) {
        int jv = tid + c * 256;
        __half2 p0 = __floats2half2_rn(e[c * 4 + 0] * rinv, e[c * 4 + 1] * rinv);
        __half2 p1 = __floats2half2_rn(e[c * 4 + 2] * rinv, e[c * 4 + 3] * rinv);
        *(uint2*)(prow + jv * 4) = make_uint2(*(uint32_t*)&p0, *(uint32_t*)&p1);
    }
}

// ============================================================
// Kernel 4: out = elu(P @ Wh), fp16 mma + ldmatrix.
//   BM=128, BN=128, BK=32, NSTAGE=4, single barrier per ktile.
// ============================================================
#define AV_STRIDE 40
#define AV_BUF (128 * AV_STRIDE)
#define AV_NSTAGE 4

__global__ __launch_bounds__(256, 2) void k_av(float* __restrict__ out) {
    extern __shared__ __half sm[];
    __half* Asm = sm;
    __half* Bsm = sm + AV_NSTAGE * AV_BUF;

    int b  = blockIdx.y >> 1;
    int n0 = (blockIdx.y & 1) * 128;
    int m0 = blockIdx.x * 128;
    int tid  = threadIdx.x;
    int wid  = tid >> 5, lane = tid & 31;
    int g = lane >> 2, tig = lane & 3;
    int warpM = wid >> 2;
    int warpN = wid & 3;

    const __half* Pb   = g_P   + ((size_t)b * 2048 + m0) * 2048;
    const __half* WhTb = g_WhT + ((size_t)b * 256 + n0) * 2048;

    const __half* a_src[2]; uint32_t a_dst[2];
    const __half* b_src[2]; uint32_t b_dst[2];
#pragma unroll
    for (int p = 0; p < 2; p++) {
        int c = tid + p * 256;
        int row = c >> 2, q = c & 3;
        a_src[p] = Pb   + (size_t)row * 2048 + q * 8;
        a_dst[p] = sptr(Asm + row * AV_STRIDE + q * 8);
        b_src[p] = WhTb + (size_t)row * 2048 + q * 8;
        b_dst[p] = sptr(Bsm + row * AV_STRIDE + q * 8);
    }

    uint32_t a_ld[4][2], b_ld[2][2];
    {
        int arow = lane & 15;
        int akh  = (lane >> 4) * 8;
        int brow = (lane & 7) + ((lane >> 4) & 1) * 8;
        int bkh  = ((lane >> 3) & 1) * 8;
#pragma unroll
        for (int kc = 0; kc < 2; kc++) {
#pragma unroll
            for (int mt = 0; mt < 4; mt++)
                a_ld[mt][kc] = sptr(Asm +
                    (warpM * 64 + mt * 16 + arow) * AV_STRIDE + kc * 16 + akh);
#pragma unroll
            for (int p = 0; p < 2; p++)
                b_ld[p][kc] = sptr(Bsm +
                    (warpN * 32 + p * 16 + brow) * AV_STRIDE + kc * 16 + bkh);
        }
    }

    float acc[4][4][4];
#pragma unroll
    for (int mt = 0; mt < 4; mt++)
#pragma unroll
        for (int nt = 0; nt < 4; nt++)
#pragma unroll
            for (int c = 0; c < 4; c++) acc[mt][nt][c] = 0.0f;

    const uint32_t BUFB = AV_BUF * 2;

    auto issue_tile = [&](int k0, int st) {
#pragma unroll
        for (int p = 0; p < 2; p++) {
            CP_ASYNC16(a_dst[p] + st * BUFB, a_src[p] + k0);
            CP_ASYNC16(b_dst[p] + st * BUFB, b_src[p] + k0);
        }
        CP_COMMIT();
    };

    issue_tile(0, 0);
    issue_tile(32, 1);
    issue_tile(64, 2);

#pragma unroll 1
    for (int t = 0; t < 64; t++) {
        int st = t & 3;
        if (t < 62)       { CP_WAIT2(); }
        else if (t == 62) { CP_WAIT1(); }
        else              { CP_WAIT0(); }
        __syncthreads();
        if (t + 3 < 64) issue_tile((t + 3) * 32, (t + 3) & 3);

        uint32_t sb = st * BUFB;

#pragma unroll
        for (int kc = 0; kc < 2; kc++) {
            uint32_t afr[4][4];
#pragma unroll
            for (int mt = 0; mt < 4; mt++)
                ldsm_x4(afr[mt][0], afr[mt][1], afr[mt][2], afr[mt][3],
                        a_ld[mt][kc] + sb);
            uint32_t bfr[4][2];
#pragma unroll
            for (int p = 0; p < 2; p++) {
                uint32_t r0, r1, r2, r3;
                ldsm_x4(r0, r1, r2, r3, b_ld[p][kc] + sb);
                bfr[2 * p][0] = r0;     bfr[2 * p][1] = r1;
                bfr[2 * p + 1][0] = r2; bfr[2 * p + 1][1] = r3;
            }
#pragma unroll
            for (int mt = 0; mt < 4; mt++)
#pragma unroll
                for (int nt = 0; nt < 4; nt++)
                    mma_f16(acc[mt][nt], afr[mt], bfr[nt]);
        }
    }

#pragma unroll
    for (int mt = 0; mt < 4; mt++) {
#pragma unroll
        for (int nt = 0; nt < 4; nt++) {
            int m = m0 + warpM * 64 + mt * 16 + g;
            int n = n0 + warpN * 32 + nt * 8 + 2 * tig;
            float c0 = acc[mt][nt][0], c1 = acc[mt][nt][1];
            float c2 = acc[mt][nt][2], c3 = acc[mt][nt][3];
            c0 = (c0 > 0.0f) ? c0 : expm1f(c0);
            c1 = (c1 > 0.0f) ? c1 : expm1f(c1);
            c2 = (c2 > 0.0f) ? c2 : expm1f(c2);
            c3 = (c3 > 0.0f) ? c3 : expm1f(c3);
            float* o0 = out + ((size_t)b * 2048 + m) * 256 + n;
            float* o1 = out + ((size_t)b * 2048 + m + 8) * 256 + n;
            *(float2*)o0 = make_float2(c0, c1);
            *(float2*)o1 = make_float2(c2, c3);
        }
    }
}

// ============================================================
extern "C" void kernel_launch(void* const* d_in, const int* in_sizes, int n_in,
                              void* d_out, int out_size) {
    const float* h   = (const float*)d_in[0];
    const int*   adj = (const int*)  d_in[1];
    const float* W   = (const float*)d_in[2];
    const float* a   = (const float*)d_in[3];
    float* out = (float*)d_out;

    const int AV_SMEM = AV_NSTAGE * 2 * AV_BUF * 2;                  // 81920 B
    const int G_SMEM  = G_NSTAGE * 2 * (G_ABUF + G_BBUF) * 2;        // 92160 B
    static int attr_done = 0;
    if (!attr_done) {
        cudaFuncSetAttribute(k_av, cudaFuncAttributeMaxDynamicSharedMemorySize,
                             AV_SMEM);
        cudaFuncSetAttribute(k_gemm16, cudaFuncAttributeMaxDynamicSharedMemorySize,
                             G_SMEM);
        attr_done = 1;
    }

    k_wa<<<1, 256>>>(W, a);
    k_s<<<16384 / 8, 256>>>(h);

    k_split <<<4096, 256>>>(h);      // 16384*256/4/256
    k_splitW<<<64,   256>>>(W);      // 256*256/4/256

    dim3 g2(2048 / 64, 16);
    k_gemm16<<<g2, 256, G_SMEM>>>();

    dim3 g3(2048, 8);
    k_softmax<<<g3, 256>>>(adj);

    dim3 g4(2048 / 128, 16);
    k_av<<<g4, 256, AV_SMEM>>>(out);
}

// round 11
// speedup vs baseline: 1.2636x; 1.2636x over previous
#include <cuda_runtime.h>
#include <cuda_fp16.h>
#include <cstdint>

#define NEG_BIG (-9000000000000000.0f)
#define LEAKY 0.2f

// ---- scratch (static device globals; no runtime allocation) ----
__device__ __half g_WhT [8ul * 256 * 2048];    // [b][n][i] half (B operand / AV)
__device__ __half g_P   [8ul * 2048 * 2048];   // normalized attention, half
__device__ float  g_s1  [8 * 2048];
__device__ float  g_s2  [8 * 2048];
__device__ float  g_wa1 [256];
__device__ float  g_wa2 [256];

__device__ __forceinline__ unsigned sptr(const void* p) {
    return (unsigned)__cvta_generic_to_shared(p);
}
#define CP_ASYNC16(dst, src) \
    asm volatile("cp.async.cg.shared.global [%0], [%1], 16;" :: "r"(dst), "l"(src))
#define CP_COMMIT() asm volatile("cp.async.commit_group;")
#define CP_WAIT0()  asm volatile("cp.async.wait_group 0;")
#define CP_WAIT1()  asm volatile("cp.async.wait_group 1;")
#define CP_WAIT2()  asm volatile("cp.async.wait_group 2;")

__device__ __forceinline__ void ldsm_x4(uint32_t& r0, uint32_t& r1,
                                        uint32_t& r2, uint32_t& r3,
                                        uint32_t addr) {
    asm volatile("ldmatrix.sync.aligned.m8n8.x4.shared.b16 {%0,%1,%2,%3}, [%4];"
                 : "=r"(r0), "=r"(r1), "=r"(r2), "=r"(r3) : "r"(addr));
}
__device__ __forceinline__ void mma_f16(float* d, const uint32_t* a, const uint32_t* b) {
    asm volatile(
        "mma.sync.aligned.m16n8k16.row.col.f32.f16.f16.f32 "
        "{%0,%1,%2,%3}, {%4,%5,%6,%7}, {%8,%9}, {%0,%1,%2,%3};"
        : "+f"(d[0]), "+f"(d[1]), "+f"(d[2]), "+f"(d[3])
        : "r"(a[0]), "r"(a[1]), "r"(a[2]), "r"(a[3]), "r"(b[0]), "r"(b[1]));
}

// ============================================================
// Kernel 0: wa1 = W^T a1, wa2 = W^T a2   (single block)
// ============================================================
__global__ void k_wa(const float* __restrict__ W, const float* __restrict__ a) {
    int f = threadIdx.x;
    float v1 = 0.0f, v2 = 0.0f;
#pragma unroll 8
    for (int o = 0; o < 256; o++) {
        float w = W[o * 256 + f];
        v1 = fmaf(w, __ldg(a + o),       v1);
        v2 = fmaf(w, __ldg(a + 256 + o), v2);
    }
    g_wa1[f] = v1;
    g_wa2[f] = v2;
}

// ============================================================
// Kernel 1: s1[r] = h[r,:]·wa1 ; s2[r] = h[r,:]·wa2  (exact fp32)
// ============================================================
__global__ void k_s(const float* __restrict__ h) {
    int row  = blockIdx.x * 8 + (threadIdx.x >> 5);
    int lane = threadIdx.x & 31;
    const float* hr = h + (size_t)row * 256;

    float v1 = 0.0f, v2 = 0.0f;
#pragma unroll
    for (int k = lane; k < 256; k += 32) {
        float x = hr[k];
        v1 = fmaf(x, g_wa1[k], v1);
        v2 = fmaf(x, g_wa2[k], v2);
    }
#pragma unroll
    for (int off = 16; off; off >>= 1) {
        v1 += __shfl_down_sync(0xffffffffu, v1, off);
        v2 += __shfl_down_sync(0xffffffffu, v2, off);
    }
    if (lane == 0) { g_s1[row] = v1; g_s2[row] = v2; }
}

// ============================================================
// Kernel 2: WhT[b][n][i] = sum_f W[n][f] h[b][i][f]  via fp16 mma
//   with hi/lo split (3-pass): fp32-quality, fp16 stored.
//   (R9 version: in-kernel split, reads fp32 W/h.)
// ============================================================
__global__ __launch_bounds__(256) void k_gemm16(const float* __restrict__ W,
                                                const float* __restrict__ h) {
    __shared__ __half Ah[128 * 40], Al[128 * 40];   // W hi/lo   [n][k]
    __shared__ __half Bh[64 * 40],  Bl[64 * 40];    // h hi/lo   [i][k]

    int tid = threadIdx.x;
    int wid = tid >> 5, lane = tid & 31;
    int g = lane >> 2, tig = lane & 3;
    int warpM = wid & 3;
    int warpN = wid >> 2;

    int i0 = blockIdx.x * 64;
    int b  = blockIdx.y >> 1;
    int n0 = (blockIdx.y & 1) * 128;

    const float* aptr[4]; int aoff[4];
#pragma unroll
    for (int p = 0; p < 4; p++) {
        int idx = tid + p * 256;
        int row = idx >> 3, q = idx & 7;
        aptr[p] = W + (size_t)(n0 + row) * 256 + q * 4;
        aoff[p] = row * 40 + q * 4;
    }
    const float* bptr[2]; int boff[2];
#pragma unroll
    for (int p = 0; p < 2; p++) {
        int idx = tid + p * 256;
        int row = idx >> 3, q = idx & 7;
        bptr[p] = h + ((size_t)(b * 2048 + i0 + row)) * 256 + q * 4;
        boff[p] = row * 40 + q * 4;
    }

    float4 areg[4], breg[2];
#pragma unroll
    for (int p = 0; p < 4; p++) areg[p] = *(const float4*)(aptr[p]);
#pragma unroll
    for (int p = 0; p < 2; p++) breg[p] = *(const float4*)(bptr[p]);

    float acc[2][4][4];
#pragma unroll
    for (int mt = 0; mt < 2; mt++)
#pragma unroll
        for (int nt = 0; nt < 4; nt++)
#pragma unroll
            for (int c = 0; c < 4; c++) acc[mt][nt][c] = 0.0f;

    int arow = lane & 15;
    int akh  = (lane >> 4) * 8;
    int brow = (lane & 7) + ((lane >> 4) & 1) * 8;
    int bkh  = ((lane >> 3) & 1) * 8;

    for (int t = 0; t < 8; t++) {
#pragma unroll
        for (int p = 0; p < 4; p++) {
            float4 v = areg[p];
            __half hx = __float2half_rn(v.x), hy = __float2half_rn(v.y);
            __half hz = __float2half_rn(v.z), hw = __float2half_rn(v.w);
            __half lx = __float2half_rn(v.x - __half2float(hx));
            __half ly = __float2half_rn(v.y - __half2float(hy));
            __half lz = __float2half_rn(v.z - __half2float(hz));
            __half lw = __float2half_rn(v.w - __half2float(hw));
            __half2 h01 = __halves2half2(hx, hy), h23 = __halves2half2(hz, hw);
            __half2 l01 = __halves2half2(lx, ly), l23 = __halves2half2(lz, lw);
            *(uint2*)(Ah + aoff[p]) = make_uint2(*(uint32_t*)&h01, *(uint32_t*)&h23);
            *(uint2*)(Al + aoff[p]) = make_uint2(*(uint32_t*)&l01, *(uint32_t*)&l23);
        }
#pragma unroll
        for (int p = 0; p < 2; p++) {
            float4 v = breg[p];
            __half hx = __float2half_rn(v.x), hy = __float2half_rn(v.y);
            __half hz = __float2half_rn(v.z), hw = __float2half_rn(v.w);
            __half lx = __float2half_rn(v.x - __half2float(hx));
            __half ly = __float2half_rn(v.y - __half2float(hy));
            __half lz = __float2half_rn(v.z - __half2float(hz));
            __half lw = __float2half_rn(v.w - __half2float(hw));
            __half2 h01 = __halves2half2(hx, hy), h23 = __halves2half2(hz, hw);
            __half2 l01 = __halves2half2(lx, ly), l23 = __halves2half2(lz, lw);
            *(uint2*)(Bh + boff[p]) = make_uint2(*(uint32_t*)&h01, *(uint32_t*)&h23);
            *(uint2*)(Bl + boff[p]) = make_uint2(*(uint32_t*)&l01, *(uint32_t*)&l23);
        }
        __syncthreads();

        if (t + 1 < 8) {
            int k0 = (t + 1) * 32;
#pragma unroll
            for (int p = 0; p < 4; p++) areg[p] = *(const float4*)(aptr[p] + k0);
#pragma unroll
            for (int p = 0; p < 2; p++) breg[p] = *(const float4*)(bptr[p] + k0);
        }

#pragma unroll
        for (int kc = 0; kc < 2; kc++) {
            uint32_t afh[2][4], afl[2][4];
#pragma unroll
            for (int mt = 0; mt < 2; mt++) {
                int r = (warpM * 32 + mt * 16 + arow) * 40 + kc * 16 + akh;
                ldsm_x4(afh[mt][0], afh[mt][1], afh[mt][2], afh[mt][3], sptr(Ah + r));
                ldsm_x4(afl[mt][0], afl[mt][1], afl[mt][2], afl[mt][3], sptr(Al + r));
            }
            uint32_t bfh[4][2], bfl[4][2];
#pragma unroll
            for (int p = 0; p < 2; p++) {
                int r = (warpN * 32 + p * 16 + brow) * 40 + kc * 16 + bkh;
                uint32_t r0, r1, r2, r3;
                ldsm_x4(r0, r1, r2, r3, sptr(Bh + r));
                bfh[2 * p][0] = r0;     bfh[2 * p][1] = r1;
                bfh[2 * p + 1][0] = r2; bfh[2 * p + 1][1] = r3;
                ldsm_x4(r0, r1, r2, r3, sptr(Bl + r));
                bfl[2 * p][0] = r0;     bfl[2 * p][1] = r1;
                bfl[2 * p + 1][0] = r2; bfl[2 * p + 1][1] = r3;
            }
#pragma unroll
            for (int mt = 0; mt < 2; mt++)
#pragma unroll
                for (int nt = 0; nt < 4; nt++) {
                    mma_f16(acc[mt][nt], afh[mt], bfh[nt]);
                    mma_f16(acc[mt][nt], afh[mt], bfl[nt]);
                    mma_f16(acc[mt][nt], afl[mt], bfh[nt]);
                }
        }
        __syncthreads();
    }

#pragma unroll
    for (int mt = 0; mt < 2; mt++) {
#pragma unroll
        for (int nt = 0; nt < 4; nt++) {
            int n = n0 + warpM * 32 + mt * 16 + g;
            int i = i0 + warpN * 32 + nt * 8 + 2 * tig;
            __half2 v0 = __floats2half2_rn(acc[mt][nt][0], acc[mt][nt][1]);
            __half2 v1 = __floats2half2_rn(acc[mt][nt][2], acc[mt][nt][3]);
            *(__half2*)(g_WhT + ((size_t)(b * 256 + n))     * 2048 + i) = v0;
            *(__half2*)(g_WhT + ((size_t)(b * 256 + n + 8)) * 2048 + i) = v1;
        }
    }
}

// ============================================================
// Kernel 3: masked-leaky softmax, register-resident
// ============================================================
__global__ __launch_bounds__(256) void k_softmax(const int* __restrict__ adj) {
    __shared__ float redm[8];
    __shared__ float redsum[8];

    int i = blockIdx.x;
    int b = blockIdx.y;
    int tid  = threadIdx.x;
    int wid  = tid >> 5;
    int lane = tid & 31;

    const int4*  arow4 = (const int4*)(adj + ((size_t)b * 2048 + i) * 2048);
    const float* s2    = g_s2 + (size_t)b * 2048;
    float s1i = g_s1[(size_t)b * 2048 + i];

    float e[8];
    float lm = -INFINITY;
#pragma unroll
    for (int c = 0; c < 2; c++) {
        int jv = tid + c * 256;
        int4   av  = arow4[jv];
        float4 s2v = *(const float4*)(s2 + jv * 4);
        float e0 = s1i + s2v.x, e1 = s1i + s2v.y;
        float e2 = s1i + s2v.z, e3 = s1i + s2v.w;
        e0 = (e0 > 0.0f) ? e0 : LEAKY * e0;
        e1 = (e1 > 0.0f) ? e1 : LEAKY * e1;
        e2 = (e2 > 0.0f) ? e2 : LEAKY * e2;
        e3 = (e3 > 0.0f) ? e3 : LEAKY * e3;
        e0 = av.x ? e0 : NEG_BIG;
        e1 = av.y ? e1 : NEG_BIG;
        e2 = av.z ? e2 : NEG_BIG;
        e3 = av.w ? e3 : NEG_BIG;
        e[c * 4 + 0] = e0; e[c * 4 + 1] = e1;
        e[c * 4 + 2] = e2; e[c * 4 + 3] = e3;
        lm = fmaxf(lm, fmaxf(fmaxf(e0, e1), fmaxf(e2, e3)));
    }
#pragma unroll
    for (int off = 16; off; off >>= 1)
        lm = fmaxf(lm, __shfl_xor_sync(0xffffffffu, lm, off));
    if (lane == 0) redm[wid] = lm;
    __syncthreads();

    float m = redm[0];
#pragma unroll
    for (int w = 1; w < 8; w++) m = fmaxf(m, redm[w]);

    float ls = 0.0f;
#pragma unroll
    for (int t = 0; t < 8; t++) {
        float p = __expf(e[t] - m);
        e[t] = p;
        ls += p;
    }
#pragma unroll
    for (int off = 16; off; off >>= 1)
        ls += __shfl_xor_sync(0xffffffffu, ls, off);
    if (lane == 0) redsum[wid] = ls;
    __syncthreads();

    float sum = 0.0f;
#pragma unroll
    for (int w = 0; w < 8; w++) sum += redsum[w];
    float rinv = 1.0f / sum;

    __half* prow = g_P + ((size_t)b * 2048 + i) * 2048;
#pragma unroll
    for (int c = 0; c < 2; c++) {
        int jv = tid + c * 256;
        __half2 p0 = __floats2half2_rn(e[c * 4 + 0] * rinv, e[c * 4 + 1] * rinv);
        __half2 p1 = __floats2half2_rn(e[c * 4 + 2] * rinv, e[c * 4 + 3] * rinv);
        *(uint2*)(prow + jv * 4) = make_uint2(*(uint32_t*)&p0, *(uint32_t*)&p1);
    }
}

// ============================================================
// Kernel 4: out = elu(P @ Wh), fp16 mma + ldmatrix.
//   BM=128, BN=128, BK=32, NSTAGE=4, single barrier per ktile.
// ============================================================
#define AV_STRIDE 40
#define AV_BUF (128 * AV_STRIDE)
#define AV_NSTAGE 4

__global__ __launch_bounds__(256, 2) void k_av(float* __restrict__ out) {
    extern __shared__ __half sm[];
    __half* Asm = sm;
    __half* Bsm = sm + AV_NSTAGE * AV_BUF;

    int b  = blockIdx.y >> 1;
    int n0 = (blockIdx.y & 1) * 128;
    int m0 = blockIdx.x * 128;
    int tid  = threadIdx.x;
    int wid  = tid >> 5, lane = tid & 31;
    int g = lane >> 2, tig = lane & 3;
    int warpM = wid >> 2;
    int warpN = wid & 3;

    const __half* Pb   = g_P   + ((size_t)b * 2048 + m0) * 2048;
    const __half* WhTb = g_WhT + ((size_t)b * 256 + n0) * 2048;

    const __half* a_src[2]; uint32_t a_dst[2];
    const __half* b_src[2]; uint32_t b_dst[2];
#pragma unroll
    for (int p = 0; p < 2; p++) {
        int c = tid + p * 256;
        int row = c >> 2, q = c & 3;
        a_src[p] = Pb   + (size_t)row * 2048 + q * 8;
        a_dst[p] = sptr(Asm + row * AV_STRIDE + q * 8);
        b_src[p] = WhTb + (size_t)row * 2048 + q * 8;
        b_dst[p] = sptr(Bsm + row * AV_STRIDE + q * 8);
    }

    uint32_t a_ld[4][2], b_ld[2][2];
    {
        int arow = lane & 15;
        int akh  = (lane >> 4) * 8;
        int brow = (lane & 7) + ((lane >> 4) & 1) * 8;
        int bkh  = ((lane >> 3) & 1) * 8;
#pragma unroll
        for (int kc = 0; kc < 2; kc++) {
#pragma unroll
            for (int mt = 0; mt < 4; mt++)
                a_ld[mt][kc] = sptr(Asm +
                    (warpM * 64 + mt * 16 + arow) * AV_STRIDE + kc * 16 + akh);
#pragma unroll
            for (int p = 0; p < 2; p++)
                b_ld[p][kc] = sptr(Bsm +
                    (warpN * 32 + p * 16 + brow) * AV_STRIDE + kc * 16 + bkh);
        }
    }

    float acc[4][4][4];
#pragma unroll
    for (int mt = 0; mt < 4; mt++)
#pragma unroll
        for (int nt = 0; nt < 4; nt++)
#pragma unroll
            for (int c = 0; c < 4; c++) acc[mt][nt][c] = 0.0f;

    const uint32_t BUFB = AV_BUF * 2;

    auto issue_tile = [&](int k0, int st) {
#pragma unroll
        for (int p = 0; p < 2; p++) {
            CP_ASYNC16(a_dst[p] + st * BUFB, a_src[p] + k0);
            CP_ASYNC16(b_dst[p] + st * BUFB, b_src[p] + k0);
        }
        CP_COMMIT();
    };

    issue_tile(0, 0);
    issue_tile(32, 1);
    issue_tile(64, 2);

#pragma unroll 1
    for (int t = 0; t < 64; t++) {
        int st = t & 3;
        if (t < 62)       { CP_WAIT2(); }
        else if (t == 62) { CP_WAIT1(); }
        else              { CP_WAIT0(); }
        __syncthreads();
        if (t + 3 < 64) issue_tile((t + 3) * 32, (t + 3) & 3);

        uint32_t sb = st * BUFB;

#pragma unroll
        for (int kc = 0; kc < 2; kc++) {
            uint32_t afr[4][4];
#pragma unroll
            for (int mt = 0; mt < 4; mt++)
                ldsm_x4(afr[mt][0], afr[mt][1], afr[mt][2], afr[mt][3],
                        a_ld[mt][kc] + sb);
            uint32_t bfr[4][2];
#pragma unroll
            for (int p = 0; p < 2; p++) {
                uint32_t r0, r1, r2, r3;
                ldsm_x4(r0, r1, r2, r3, b_ld[p][kc] + sb);
                bfr[2 * p][0] = r0;     bfr[2 * p][1] = r1;
                bfr[2 * p + 1][0] = r2; bfr[2 * p + 1][1] = r3;
            }
#pragma unroll
            for (int mt = 0; mt < 4; mt++)
#pragma unroll
                for (int nt = 0; nt < 4; nt++)
                    mma_f16(acc[mt][nt], afr[mt], bfr[nt]);
        }
    }

#pragma unroll
    for (int mt = 0; mt < 4; mt++) {
#pragma unroll
        for (int nt = 0; nt < 4; nt++) {
            int m = m0 + warpM * 64 + mt * 16 + g;
            int n = n0 + warpN * 32 + nt * 8 + 2 * tig;
            float c0 = acc[mt][nt][0], c1 = acc[mt][nt][1];
            float c2 = acc[mt][nt][2], c3 = acc[mt][nt][3];
            c0 = (c0 > 0.0f) ? c0 : expm1f(c0);
            c1 = (c1 > 0.0f) ? c1 : expm1f(c1);
            c2 = (c2 > 0.0f) ? c2 : expm1f(c2);
            c3 = (c3 > 0.0f) ? c3 : expm1f(c3);
            float* o0 = out + ((size_t)b * 2048 + m) * 256 + n;
            float* o1 = out + ((size_t)b * 2048 + m + 8) * 256 + n;
            *(float2*)o0 = make_float2(c0, c1);
            *(float2*)o1 = make_float2(c2, c3);
        }
    }
}

// ============================================================
extern "C" void kernel_launch(void* const* d_in, const int* in_sizes, int n_in,
                              void* d_out, int out_size) {
    const float* h   = (const float*)d_in[0];
    const int*   adj = (const int*)  d_in[1];
    const float* W   = (const float*)d_in[2];
    const float* a   = (const float*)d_in[3];
    float* out = (float*)d_out;

    const int AV_SMEM = AV_NSTAGE * 2 * AV_BUF * 2;   // 81920 B
    static cudaStream_t sB = nullptr;
    static cudaEvent_t evFork = nullptr, evJoin = nullptr;
    if (sB == nullptr) {
        cudaFuncSetAttribute(k_av, cudaFuncAttributeMaxDynamicSharedMemorySize,
                             AV_SMEM);
        cudaStreamCreateWithFlags(&sB, cudaStreamNonBlocking);
        cudaEventCreateWithFlags(&evFork, cudaEventDisableTiming);
        cudaEventCreateWithFlags(&evJoin, cudaEventDisableTiming);
    }

    // fork: branch B (independent of s1/s2 chain) runs k_gemm16
    cudaEventRecord(evFork, 0);
    cudaStreamWaitEvent(sB, evFork, 0);

    dim3 g2(2048 / 64, 16);
    k_gemm16<<<g2, 256, 0, sB>>>(W, h);
    cudaEventRecord(evJoin, sB);

    // branch A on default stream: wa -> s -> softmax
    k_wa<<<1, 256>>>(W, a);
    k_s<<<16384 / 8, 256>>>(h);
    dim3 g3(2048, 8);
    k_softmax<<<g3, 256>>>(adj);

    // join, then AV
    cudaStreamWaitEvent(0, evJoin, 0);
    dim3 g4(2048 / 128, 16);
    k_av<<<g4, 256, AV_SMEM>>>(out);
}